// round 11
// baseline (speedup 1.0000x reference)
#include <cuda_runtime.h>
#include <cuda_bf16.h>
#include <mma.h>

using namespace nvcuda;
typedef unsigned int u32;
typedef unsigned char u8;
typedef __nv_bfloat16 bf16;

// ---- problem constants ----
#define NITER 21        // floor(1/0.05)=20 scaled steps + 1 unscaled add
#define DT    0.05f
#define THREADS 512

// ---- global images ----
#define XN (8192u*384u)
#define HN (8192u*512u)
__device__ __align__(16) bf16 g_X [2u*XN];        // [m][384] hi | lo
__device__ __align__(16) bf16 g_H [2u*HN];        // [m][512] hi | lo (H1 then H2)
__device__ __align__(16) bf16 g_W1[2u*196608u];   // [512 n][384 k] hi | lo
__device__ __align__(16) bf16 g_W2[2u*262144u];   // [512 n][512 k]
__device__ __align__(16) bf16 g_W3[2u*131072u];   // [256 n][512 k]
__device__ float g_State[8192u*256u];             // exact fp32 state [m][s]

// ---- smem layout (bytes) ----
// A: 2 buf x 2 part x 64 rows x 48B   (row = 16 bf16 padded to 24 elems)
#define SA_B   0u
#define SA_BUF 6144u
#define SA_PRT 3072u
// B: 2 buf x 2 part x 512 rows x 48B
#define SB_B   12288u
#define SB_BUF 49152u
#define SB_PRT 24576u
#define SNC_B  110592u   // bounce: 16 warps x 256 f32 = 16KB
#define SB1_B  126976u
#define SB2_B  129024u
#define SB3_B  131072u
#define SMEM_SZ 132096

using FragA = wmma::fragment<wmma::matrix_a, 16, 16, 16, bf16, wmma::row_major>;
using FragB = wmma::fragment<wmma::matrix_b, 16, 16, 16, bf16, wmma::col_major>;
using FragC = wmma::fragment<wmma::accumulator, 16, 16, 16, float>;

__device__ __forceinline__ void cp16(u32 dst, const void* src) {
    asm volatile("cp.async.ca.shared.global [%0], [%1], 16;" :: "r"(dst), "l"(src));
}
#define CP_COMMIT() asm volatile("cp.async.commit_group;" ::: "memory")

__device__ __forceinline__ void bsplit(float v, bf16& h, bf16& l) {
    h = __float2bfloat16(v);
    l = __float2bfloat16(v - __bfloat162float(h));
}

// ---------- prep kernels ----------
__global__ void prep_w(const float* __restrict__ W1, const float* __restrict__ W2,
                       const float* __restrict__ W3) {
    u32 i = blockIdx.x * blockDim.x + threadIdx.x;
    if (i < 196608u) {  // W1 [384][512] -> [n=512][k=384]
        u32 k = i >> 9, n = i & 511u;
        bf16 h, l; bsplit(W1[i], h, l);
        g_W1[n*384u + k] = h; g_W1[196608u + n*384u + k] = l;
    }
    if (i < 262144u) {  // W2 [512][512] -> [512][512]
        u32 k = i >> 9, n = i & 511u;
        bf16 h, l; bsplit(W2[i], h, l);
        g_W2[n*512u + k] = h; g_W2[262144u + n*512u + k] = l;
    }
    if (i < 131072u) {  // W3 [512][256] -> [n=256][k=512]
        u32 k = i >> 8, n = i & 255u;
        bf16 h, l; bsplit(W3[i], h, l);
        g_W3[n*512u + k] = h; g_W3[131072u + n*512u + k] = l;
    }
}
__global__ void prep_x(const float* __restrict__ state, const float* __restrict__ user) {
    u32 i = blockIdx.x * blockDim.x + threadIdx.x;
    if (i >= 8192u*384u) return;
    u32 m = i / 384u, f = i - m*384u;
    float v;
    if (f < 256u) { v = state[m*256u + f]; g_State[m*256u + f] = v; }
    else          { v = user[m*128u + (f - 256u)]; }
    bf16 h, l; bsplit(v, h, l);
    g_X[i] = h; g_X[XN + i] = l;
}

// ---------- staging ----------
__device__ __forceinline__ void stage_A(u32 dst, const bf16* __restrict__ img,
                                        u32 ldk, u32 partN, u32 m0, u32 k0, u32 tid) {
    if (tid < 256) {
        u32 part = tid >> 7, rr = (tid >> 1) & 63u, ch = tid & 1u;
        cp16(dst + part*SA_PRT + rr*48u + ch*16u,
             img + (size_t)part*partN + (size_t)(m0 + rr)*ldk + k0 + ch*8u);
    }
}
template<u32 NR>
__device__ __forceinline__ void stage_B(u32 dst, const bf16* __restrict__ img,
                                        u32 ldk, u32 partN, u32 k0, u32 tid) {
#pragma unroll
    for (u32 e = 0; e < NR/128u; ++e) {
        u32 idx = tid + e*512u;
        u32 part = idx / (NR*2u), rem = idx % (NR*2u), n = rem >> 1, ch = rem & 1u;
        cp16(dst + part*SB_PRT + n*48u + ch*16u,
             img + (size_t)part*partN + (size_t)n*ldk + k0 + ch*8u);
    }
}

// ---------- GEMM pass: C[64 x NT*64] = A[64 x NKT*16] * B^T, 3-split bf16 ----------
template<int NKT, int NT>
__device__ __forceinline__ void run_layer(
    const bf16* __restrict__ Aimg, u32 aldk, u32 apartN,
    const bf16* __restrict__ Bimg, u32 bldk, u32 bpartN,
    u32 m0, u8* smp, u32 smb, u32 tid, FragC (&c)[8])
{
#pragma unroll
    for (int t = 0; t < NT; ++t) wmma::fill_fragment(c[t], 0.0f);
    const u32 warp = tid >> 5;
    const u32 nc0 = (warp & 3u) * (u32)(NT * 16);
    stage_A(smb + SA_B, Aimg, aldk, apartN, m0, 0u, tid);
    stage_B<NT*64>(smb + SB_B, Bimg, bldk, bpartN, 0u, tid);
    CP_COMMIT();
#pragma unroll 1
    for (int kt = 0; kt < NKT; ++kt) {
        u32 buf = (u32)kt & 1u;
        if (kt + 1 < NKT) {
            stage_A(smb + SA_B + (buf^1u)*SA_BUF, Aimg, aldk, apartN, m0, (u32)(kt+1)*16u, tid);
            stage_B<NT*64>(smb + SB_B + (buf^1u)*SB_BUF, Bimg, bldk, bpartN, (u32)(kt+1)*16u, tid);
            CP_COMMIT();
            asm volatile("cp.async.wait_group 1;" ::: "memory");
        } else {
            asm volatile("cp.async.wait_group 0;" ::: "memory");
        }
        __syncthreads();
        const bf16* sa = (const bf16*)(smp + SA_B + buf*SA_BUF) + (warp >> 2)*16u*24u;
        FragA ah, al;
        wmma::load_matrix_sync(ah, sa, 24);
        wmma::load_matrix_sync(al, sa + 1536u, 24);   // lo part (+3072B)
        const bf16* sb = (const bf16*)(smp + SB_B + buf*SB_BUF);
#pragma unroll
        for (int t = 0; t < NT; ++t) {
            const bf16* bp = sb + (nc0 + (u32)t*16u)*24u;
            FragB bh, bl;
            wmma::load_matrix_sync(bh, bp, 24);
            wmma::load_matrix_sync(bl, bp + 12288u, 24);  // lo part (+24576B)
            wmma::mma_sync(c[t], ah, bh, c[t]);
            wmma::mma_sync(c[t], ah, bl, c[t]);
            wmma::mma_sync(c[t], al, bh, c[t]);
        }
        __syncthreads();
    }
}

// ---------- epilogues ----------
__device__ __forceinline__ void epiH(FragC (&c)[8], const float* __restrict__ sb,
                                     float* __restrict__ bounce, u32 tid, u32 m0) {
    u32 warp = tid >> 5, lane = tid & 31u;
    u32 mr = m0 + (warp >> 2)*16u;
    u32 nc0 = (warp & 3u)*128u;
    float* bw = bounce + warp*256u;
    u32 row = lane & 15u, cg = lane >> 4;
#pragma unroll 1
    for (int t = 0; t < 8; ++t) {
        wmma::store_matrix_sync(bw, c[t], 16, wmma::mem_row_major);
        __syncwarp();
        const float* p = bw + row*16u + cg*8u;
        u32 col = nc0 + (u32)t*16u + cg*8u;
        alignas(16) bf16 hv[8], lv[8];
#pragma unroll
        for (int j = 0; j < 8; ++j) {
            float v = p[j] + sb[col + j];
            v = v / (1.0f + __expf(-v));          // SiLU
            bsplit(v, hv[j], lv[j]);
        }
        size_t gi = (size_t)(mr + row)*512u + col;
        *reinterpret_cast<uint4*>(&g_H[gi])      = *reinterpret_cast<const uint4*>(hv);
        *reinterpret_cast<uint4*>(&g_H[HN + gi]) = *reinterpret_cast<const uint4*>(lv);
        __syncwarp();
    }
}

__device__ __forceinline__ void epi3(FragC (&c)[8], const float* __restrict__ sb3,
                                     float coef, bool last, float* __restrict__ out,
                                     float* __restrict__ bounce, u32 tid, u32 m0) {
    u32 warp = tid >> 5, lane = tid & 31u;
    u32 mr = m0 + (warp >> 2)*16u;
    u32 nc0 = (warp & 3u)*64u;
    float* bw = bounce + warp*256u;
    u32 row = lane & 15u, cg = lane >> 4;
#pragma unroll 1
    for (int t = 0; t < 4; ++t) {
        wmma::store_matrix_sync(bw, c[t], 16, wmma::mem_row_major);
        __syncwarp();
        const float* p = bw + row*16u + cg*8u;
        u32 col = nc0 + (u32)t*16u + cg*8u;
        u32 m = mr + row;
        alignas(16) bf16 hv[8], lv[8];
#pragma unroll
        for (int j = 0; j < 8; ++j) {
            float x = p[j] + sb3[col + j];
            size_t si = (size_t)m*256u + col + j;
            float s = g_State[si] + coef * x;     // exact fp32 Euler state
            g_State[si] = s;
            if (last) out[si] = s;
            bsplit(s, hv[j], lv[j]);
        }
        size_t gi = (size_t)m*384u + col;         // state region of X image
        *reinterpret_cast<uint4*>(&g_X[gi])      = *reinterpret_cast<const uint4*>(hv);
        *reinterpret_cast<uint4*>(&g_X[XN + gi]) = *reinterpret_cast<const uint4*>(lv);
        __syncwarp();
    }
}

// ---------- main kernel ----------
__global__ void __launch_bounds__(THREADS, 1)
ode_mma(const float* __restrict__ b1, const float* __restrict__ b2,
        const float* __restrict__ b3, float* __restrict__ out) {
    extern __shared__ __align__(16) u8 smp[];
    u32 smb = (u32)__cvta_generic_to_shared(smp);
    u32 tid = threadIdx.x;
    u32 m0 = blockIdx.x * 64u;

    float* sb1 = (float*)(smp + SB1_B);
    float* sb2 = (float*)(smp + SB2_B);
    float* sb3 = (float*)(smp + SB3_B);
    float* bounce = (float*)(smp + SNC_B);
    sb1[tid] = b1[tid];
    sb2[tid] = b2[tid];
    if (tid < 256) sb3[tid] = b3[tid];
    __syncthreads();

    FragC c[8];
#pragma unroll 1
    for (int it = 0; it < NITER; ++it) {
        const float coef = (it == NITER - 1) ? 1.0f : DT;
        // Layer 1: X[64,384] @ W1 -> H1[64,512]
        run_layer<24, 8>(g_X, 384u, XN, g_W1, 384u, 196608u, m0, smp, smb, tid, c);
        epiH(c, sb1, bounce, tid, m0);
        __syncthreads();
        // Layer 2: H1[64,512] @ W2 -> H2 (overwrites g_H; all reads already done)
        run_layer<32, 8>(g_H, 512u, HN, g_W2, 512u, 262144u, m0, smp, smb, tid, c);
        epiH(c, sb2, bounce, tid, m0);
        __syncthreads();
        // Layer 3: H2[64,512] @ W3 -> state update
        run_layer<32, 4>(g_H, 512u, HN, g_W3, 512u, 131072u, m0, smp, smb, tid, c);
        epi3(c, sb3, coef, it == NITER - 1, out, bounce, tid, m0);
        __syncthreads();
    }
}

extern "C" void kernel_launch(void* const* d_in, const int* in_sizes, int n_in,
                              void* d_out, int out_size) {
    const float* state = (const float*)d_in[0];
    const float* user  = (const float*)d_in[1];
    const float* W1    = (const float*)d_in[2];
    const float* b1    = (const float*)d_in[3];
    const float* W2    = (const float*)d_in[4];
    const float* b2    = (const float*)d_in[5];
    const float* W3    = (const float*)d_in[6];
    const float* b3    = (const float*)d_in[7];
    float* out = (float*)d_out;

    prep_w<<<1024, 256>>>(W1, W2, W3);
    prep_x<<<12288, 256>>>(state, user);
    cudaFuncSetAttribute(ode_mma, cudaFuncAttributeMaxDynamicSharedMemorySize, SMEM_SZ);
    ode_mma<<<128, THREADS, SMEM_SZ>>>(b1, b2, b3, out);
}

// round 12
// speedup vs baseline: 1.5112x; 1.5112x over previous
#include <cuda_runtime.h>
#include <cuda_bf16.h>
#include <mma.h>

using namespace nvcuda;
typedef unsigned int u32;
typedef unsigned char u8;
typedef __nv_bfloat16 bf16;

// ---- problem constants ----
#define NITER 21        // floor(1/0.05)=20 scaled steps + 1 unscaled add
#define DT    0.05f
#define THREADS 512

// ---- global images ----
#define XN (8192u*384u)
#define HN (8192u*512u)
__device__ __align__(16) bf16 g_X [2u*XN];        // [m][384] hi | lo
__device__ __align__(16) bf16 g_H [2u*HN];        // [m][512] hi | lo
__device__ __align__(16) bf16 g_W1[2u*196608u];   // [512 n][384 k] hi | lo
__device__ __align__(16) bf16 g_W2[2u*262144u];   // [512 n][512 k]
__device__ __align__(16) bf16 g_W3[2u*131072u];   // [256 n][512 k]
__device__ float g_State[8192u*256u];             // exact fp32 state [m][s]

// ---- smem layout (bytes). Rows padded to 40 bf16 (80B) -> LDSM conflict-free ----
#define SA_B    0u
#define SA_PRT  5120u     // 64 rows x 80B
#define SA_BUF  10240u    // hi+lo
#define SB_B    20480u
#define SB_PRT  40960u    // 512 rows x 80B
#define SB_BUF  81920u
#define SNC_B   184320u   // bounce: 16 warps x 256 f32
#define SB1_B   200704u
#define SB2_B   202752u
#define SB3_B   204800u
#define SMEM_SZ 205824

using FragA = wmma::fragment<wmma::matrix_a, 16, 16, 16, bf16, wmma::row_major>;
using FragB = wmma::fragment<wmma::matrix_b, 16, 16, 16, bf16, wmma::col_major>;
using FragC = wmma::fragment<wmma::accumulator, 16, 16, 16, float>;

__device__ __forceinline__ void cp16(u32 dst, const void* src) {
    asm volatile("cp.async.ca.shared.global [%0], [%1], 16;" :: "r"(dst), "l"(src));
}
#define CP_COMMIT() asm volatile("cp.async.commit_group;" ::: "memory")
#define CP_WAIT0()  asm volatile("cp.async.wait_group 0;" ::: "memory")

__device__ __forceinline__ void bsplit(float v, bf16& h, bf16& l) {
    h = __float2bfloat16(v);
    l = __float2bfloat16(v - __bfloat162float(h));
}

// ---------- prep kernels (unchanged from R10, verified) ----------
__global__ void prep_w(const float* __restrict__ W1, const float* __restrict__ W2,
                       const float* __restrict__ W3) {
    u32 i = blockIdx.x * blockDim.x + threadIdx.x;
    if (i < 196608u) {
        u32 k = i >> 9, n = i & 511u;
        bf16 h, l; bsplit(W1[i], h, l);
        g_W1[n*384u + k] = h; g_W1[196608u + n*384u + k] = l;
    }
    if (i < 262144u) {
        u32 k = i >> 9, n = i & 511u;
        bf16 h, l; bsplit(W2[i], h, l);
        g_W2[n*512u + k] = h; g_W2[262144u + n*512u + k] = l;
    }
    if (i < 131072u) {
        u32 k = i >> 8, n = i & 255u;
        bf16 h, l; bsplit(W3[i], h, l);
        g_W3[n*512u + k] = h; g_W3[131072u + n*512u + k] = l;
    }
}
__global__ void prep_x(const float* __restrict__ state, const float* __restrict__ user) {
    u32 i = blockIdx.x * blockDim.x + threadIdx.x;
    if (i >= 8192u*384u) return;
    u32 m = i / 384u, f = i - m*384u;
    float v;
    if (f < 256u) { v = state[m*256u + f]; g_State[m*256u + f] = v; }
    else          { v = user[m*128u + (f - 256u)]; }
    bf16 h, l; bsplit(v, h, l);
    g_X[i] = h; g_X[XN + i] = l;
}

// ---------- staging (K-stage = 32) ----------
__device__ __forceinline__ void stageA(u32 dst, const bf16* __restrict__ img,
                                       u32 ldk, u32 partN, u32 m0, u32 k0, u32 tid) {
    u32 p = tid >> 8, r = (tid >> 2) & 63u, ch = tid & 3u;   // 512 chunks, 1/thread
    cp16(dst + p*SA_PRT + r*80u + ch*16u,
         img + (size_t)p*partN + (size_t)(m0 + r)*ldk + k0 + ch*8u);
}
template<u32 N>
__device__ __forceinline__ void stageB(u32 dst, const bf16* __restrict__ img,
                                       u32 ldk, u32 partN, u32 k0, u32 tid) {
#pragma unroll
    for (u32 e = 0; e < N/64u; ++e) {               // N*8 chunks total
        u32 idx = tid + e*512u;
        u32 p = idx / (N*4u), rem = idx % (N*4u), n = rem >> 2, ch = idx & 3u;
        cp16(dst + p*SB_PRT + n*80u + ch*16u,
             img + (size_t)p*partN + (size_t)n*ldk + k0 + ch*8u);
    }
}

// ---------- GEMM: C[64 x NT*16*8] = A[64 x NST*32] * B^T, bf16 3-split ----------
// Warp grid: 2 rowgroups (32m) x 8 colgroups (NT*16 n). Single sync per stage.
template<int NST, int NT>
__device__ __forceinline__ void run_layer(
    const bf16* __restrict__ Aimg, u32 aldk, u32 apartN,
    const bf16* __restrict__ Bimg, u32 bldk, u32 bpartN,
    u32 m0, u8* smp, u32 smb, u32 tid, FragC (&c)[8])
{
    constexpr u32 NC = (u32)NT * 128u;              // total N (NT*16 * 8 colgroups)
#pragma unroll
    for (int i = 0; i < 2*NT; ++i) wmma::fill_fragment(c[i], 0.0f);
    const u32 warp = tid >> 5;
    const u32 rowg = warp >> 3, colg = warp & 7u;

    stageA(smb + SA_B, Aimg, aldk, apartN, m0, 0u, tid);
    stageB<NC>(smb + SB_B, Bimg, bldk, bpartN, 0u, tid);
    CP_COMMIT();
#pragma unroll 1
    for (int st = 0; st < NST; ++st) {
        const u32 buf = (u32)st & 1u;
        CP_WAIT0();
        __syncthreads();                            // buf ready; all warps past st-1
        if (st + 1 < NST) {                         // refill other buf, overlaps compute
            stageA(smb + SA_B + (buf^1u)*SA_BUF, Aimg, aldk, apartN, m0, (u32)(st+1)*32u, tid);
            stageB<NC>(smb + SB_B + (buf^1u)*SB_BUF, Bimg, bldk, bpartN, (u32)(st+1)*32u, tid);
            CP_COMMIT();
        }
        const bf16* sa = (const bf16*)(smp + SA_B + buf*SA_BUF);
        const bf16* sb = (const bf16*)(smp + SB_B + buf*SB_BUF);
#pragma unroll
        for (int ks = 0; ks < 2; ++ks) {
            FragA ah[2], al[2];
#pragma unroll
            for (int r2 = 0; r2 < 2; ++r2) {
                const bf16* ap = sa + (rowg*32u + (u32)r2*16u)*40u + (u32)ks*16u;
                wmma::load_matrix_sync(ah[r2], ap, 40);
                wmma::load_matrix_sync(al[r2], ap + 2560u, 40);   // lo part (+5120B)
            }
#pragma unroll
            for (int t = 0; t < NT; ++t) {
                const bf16* bp = sb + (colg*(u32)NT*16u + (u32)t*16u)*40u + (u32)ks*16u;
                FragB bh, bl;
                wmma::load_matrix_sync(bh, bp, 40);
                wmma::load_matrix_sync(bl, bp + 20480u, 40);      // lo part (+40960B)
#pragma unroll
                for (int r2 = 0; r2 < 2; ++r2) {
                    wmma::mma_sync(c[r2*NT + t], ah[r2], bh, c[r2*NT + t]);
                    wmma::mma_sync(c[r2*NT + t], ah[r2], bl, c[r2*NT + t]);
                    wmma::mma_sync(c[r2*NT + t], al[r2], bh, c[r2*NT + t]);
                }
            }
        }
    }
}

// ---------- epilogues ----------
__device__ __forceinline__ void epiH(FragC (&c)[8], const float* __restrict__ sbias,
                                     float* __restrict__ bounce, u32 tid, u32 m0) {
    u32 warp = tid >> 5, lane = tid & 31u;
    u32 rowg = warp >> 3, colg = warp & 7u;
    float* bw = bounce + warp*256u;
    u32 row = lane & 15u, cg = lane >> 4;
#pragma unroll
    for (int r2 = 0; r2 < 2; ++r2)
#pragma unroll 1
    for (int t = 0; t < 4; ++t) {
        wmma::store_matrix_sync(bw, c[r2*4 + t], 16, wmma::mem_row_major);
        __syncwarp();
        const float* p = bw + row*16u + cg*8u;
        u32 col = colg*64u + (u32)t*16u + cg*8u;
        u32 m = m0 + rowg*32u + (u32)r2*16u + row;
        alignas(16) bf16 hv[8], lv[8];
#pragma unroll
        for (int j = 0; j < 8; ++j) {
            float v = p[j] + sbias[col + j];
            v = v / (1.0f + __expf(-v));            // SiLU
            bsplit(v, hv[j], lv[j]);
        }
        size_t gi = (size_t)m*512u + col;
        *reinterpret_cast<uint4*>(&g_H[gi])      = *reinterpret_cast<const uint4*>(hv);
        *reinterpret_cast<uint4*>(&g_H[HN + gi]) = *reinterpret_cast<const uint4*>(lv);
        __syncwarp();
    }
}

__device__ __forceinline__ void epi3(FragC (&c)[8], const float* __restrict__ sb3,
                                     float coef, bool last, float* __restrict__ out,
                                     float* __restrict__ bounce, u32 tid, u32 m0) {
    u32 warp = tid >> 5, lane = tid & 31u;
    u32 rowg = warp >> 3, colg = warp & 7u;
    float* bw = bounce + warp*256u;
    u32 row = lane & 15u, cg = lane >> 4;
#pragma unroll
    for (int r2 = 0; r2 < 2; ++r2)
#pragma unroll 1
    for (int t = 0; t < 2; ++t) {
        wmma::store_matrix_sync(bw, c[r2*2 + t], 16, wmma::mem_row_major);
        __syncwarp();
        const float* p = bw + row*16u + cg*8u;
        u32 col = colg*32u + (u32)t*16u + cg*8u;
        u32 m = m0 + rowg*32u + (u32)r2*16u + row;
        alignas(16) bf16 hv[8], lv[8];
#pragma unroll
        for (int j = 0; j < 8; ++j) {
            float x = p[j] + sb3[col + j];
            size_t si = (size_t)m*256u + col + j;
            float s = g_State[si] + coef * x;       // exact fp32 Euler recurrence
            g_State[si] = s;
            if (last) out[si] = s;
            bsplit(s, hv[j], lv[j]);
        }
        size_t gi = (size_t)m*384u + col;           // state region of X image
        *reinterpret_cast<uint4*>(&g_X[gi])      = *reinterpret_cast<const uint4*>(hv);
        *reinterpret_cast<uint4*>(&g_X[XN + gi]) = *reinterpret_cast<const uint4*>(lv);
        __syncwarp();
    }
}

// ---------- main kernel ----------
__global__ void __launch_bounds__(THREADS, 1)
ode_mma(const float* __restrict__ b1, const float* __restrict__ b2,
        const float* __restrict__ b3, float* __restrict__ out) {
    extern __shared__ __align__(16) u8 smp[];
    u32 smb = (u32)__cvta_generic_to_shared(smp);
    u32 tid = threadIdx.x;
    u32 m0 = blockIdx.x * 64u;

    float* sb1 = (float*)(smp + SB1_B);
    float* sb2 = (float*)(smp + SB2_B);
    float* sb3 = (float*)(smp + SB3_B);
    float* bounce = (float*)(smp + SNC_B);
    sb1[tid] = b1[tid];
    sb2[tid] = b2[tid];
    if (tid < 256) sb3[tid] = b3[tid];
    __syncthreads();

    FragC c[8];
#pragma unroll 1
    for (int it = 0; it < NITER; ++it) {
        const float coef = (it == NITER - 1) ? 1.0f : DT;
        // Layer 1: X[64,384] @ W1 -> H1[64,512]
        run_layer<12, 4>(g_X, 384u, XN, g_W1, 384u, 196608u, m0, smp, smb, tid, c);
        epiH(c, sb1, bounce, tid, m0);
        __syncthreads();
        // Layer 2: H1[64,512] @ W2 -> H2 (same image; all reads staged before epi)
        run_layer<16, 4>(g_H, 512u, HN, g_W2, 512u, 262144u, m0, smp, smb, tid, c);
        epiH(c, sb2, bounce, tid, m0);
        __syncthreads();
        // Layer 3: H2[64,512] @ W3 -> Euler state update
        run_layer<16, 2>(g_H, 512u, HN, g_W3, 512u, 131072u, m0, smp, smb, tid, c);
        epi3(c, sb3, coef, it == NITER - 1, out, bounce, tid, m0);
        __syncthreads();
    }
}

extern "C" void kernel_launch(void* const* d_in, const int* in_sizes, int n_in,
                              void* d_out, int out_size) {
    const float* state = (const float*)d_in[0];
    const float* user  = (const float*)d_in[1];
    const float* W1    = (const float*)d_in[2];
    const float* b1    = (const float*)d_in[3];
    const float* W2    = (const float*)d_in[4];
    const float* b2    = (const float*)d_in[5];
    const float* W3    = (const float*)d_in[6];
    const float* b3    = (const float*)d_in[7];
    float* out = (float*)d_out;

    prep_w<<<1024, 256>>>(W1, W2, W3);
    prep_x<<<12288, 256>>>(state, user);
    cudaFuncSetAttribute(ode_mma, cudaFuncAttributeMaxDynamicSharedMemorySize, SMEM_SZ);
    ode_mma<<<128, THREADS, SMEM_SZ>>>(b1, b2, b3, out);
}

// round 13
// speedup vs baseline: 1.5817x; 1.0466x over previous
#include <cuda_runtime.h>
#include <cuda_bf16.h>
#include <mma.h>

using namespace nvcuda;
typedef unsigned int u32;
typedef unsigned char u8;
typedef __nv_bfloat16 bf16;

#define NITER 21        // floor(1/0.05)=20 scaled steps + 1 unscaled add
#define DT    0.05f
#define THREADS 256

// ---- global images ----
#define XN (8192u*384u)
#define HN (8192u*512u)
__device__ __align__(16) bf16 g_X [2u*XN];        // [m][384] hi | lo
__device__ __align__(16) bf16 g_H1[2u*HN];        // [m][512] hi | lo
__device__ __align__(16) bf16 g_H2[2u*HN];
__device__ __align__(16) bf16 g_W1[2u*196608u];   // [512 n][384 k] hi | lo
__device__ __align__(16) bf16 g_W2[2u*262144u];   // [512 n][512 k]
__device__ __align__(16) bf16 g_W3[2u*131072u];   // [256 n][512 k]
__device__ float g_State[8192u*256u];             // exact fp32 state [m][s]
__device__ u32   g_flag[256];                     // pair handshake counters

// ---- smem (bytes). rows padded to 40 bf16 (80B): LDSM conflict-free ----
#define SA_B    0u
#define SA_PRT  5120u     // 64 rows x 80B
#define SA_BUF  10240u
#define SB_B    20480u    // 2 buf x 2 part x NR rows x 80B (NR<=256)
#define SNC_B   102400u   // bounce: 8 warps x 1KB
#define SMEM_SZ 110592

using FragA = wmma::fragment<wmma::matrix_a, 16, 16, 16, bf16, wmma::row_major>;
using FragB = wmma::fragment<wmma::matrix_b, 16, 16, 16, bf16, wmma::col_major>;
using FragC = wmma::fragment<wmma::accumulator, 16, 16, 16, float>;

__device__ __forceinline__ void cp16ca(u32 dst, const void* src) {   // weights
    asm volatile("cp.async.ca.shared.global [%0], [%1], 16;" :: "r"(dst), "l"(src));
}
__device__ __forceinline__ void cp16cg(u32 dst, const void* src) {   // activations (L1 bypass)
    asm volatile("cp.async.cg.shared.global [%0], [%1], 16;" :: "r"(dst), "l"(src));
}
#define CP_COMMIT() asm volatile("cp.async.commit_group;" ::: "memory")
#define CP_WAIT0()  asm volatile("cp.async.wait_group 0;" ::: "memory")

__device__ __forceinline__ void bsplit(float v, bf16& h, bf16& l) {
    h = __float2bfloat16(v);
    l = __float2bfloat16(v - __bfloat162float(h));
}

// ---------- merged prep kernel (also zeroes pair flags) ----------
__global__ void prep_all(const float* __restrict__ state, const float* __restrict__ user,
                         const float* __restrict__ W1, const float* __restrict__ W2,
                         const float* __restrict__ W3) {
    u32 i = blockIdx.x * blockDim.x + threadIdx.x;
    if (i < 256u) g_flag[i] = 0u;
    if (i < 196608u) {
        u32 k = i >> 9, n = i & 511u;
        bf16 h, l; bsplit(W1[i], h, l);
        g_W1[n*384u + k] = h; g_W1[196608u + n*384u + k] = l;
    }
    if (i < 262144u) {
        u32 k = i >> 9, n = i & 511u;
        bf16 h, l; bsplit(W2[i], h, l);
        g_W2[n*512u + k] = h; g_W2[262144u + n*512u + k] = l;
    }
    if (i < 131072u) {
        u32 k = i >> 8, n = i & 255u;
        bf16 h, l; bsplit(W3[i], h, l);
        g_W3[n*512u + k] = h; g_W3[131072u + n*512u + k] = l;
    }
    if (i < 8192u*384u) {
        u32 m = i / 384u, f = i - m*384u;
        float v;
        if (f < 256u) { v = state[m*256u + f]; g_State[m*256u + f] = v; }
        else          { v = user[m*128u + (f - 256u)]; }
        bf16 h, l; bsplit(v, h, l);
        g_X[i] = h; g_X[XN + i] = l;
    }
}

// ---------- pair sync (adjacent CTAs share an m-tile) ----------
__device__ __forceinline__ void pair_sync(u32 cta, int phase, u32 tid) {
    __syncthreads();
    if (tid == 0) {
        __threadfence();
        atomicAdd(&g_flag[cta], 1u);
        u32 v;
        do {
            asm volatile("ld.global.acquire.gpu.u32 %0, [%1];"
                         : "=r"(v) : "l"(&g_flag[cta ^ 1u]));
        } while ((int)v < phase);
    }
    __syncthreads();
}

// ---------- staging ----------
__device__ __forceinline__ void stageA(u32 dst, const bf16* __restrict__ img,
                                       u32 ldk, u32 partN, u32 m0, u32 k0, u32 tid) {
#pragma unroll
    for (u32 e = 0; e < 2; ++e) {       // 512 chunks / 256 threads
        u32 idx = tid + e*256u;
        u32 p = idx >> 8, r = (idx >> 2) & 63u, ch = idx & 3u;
        cp16cg(dst + p*SA_PRT + r*80u + ch*16u,
               img + (size_t)p*partN + (size_t)(m0 + r)*ldk + k0 + ch*8u);
    }
}
template<u32 NR>
__device__ __forceinline__ void stageB(u32 dst, const bf16* __restrict__ img,
                                       u32 ldk, u32 partN, u32 n0, u32 k0, u32 tid) {
#pragma unroll
    for (u32 e = 0; e < NR/32u; ++e) {  // NR*8 chunks / 256 threads
        u32 idx = tid + e*256u;
        u32 p = idx / (NR*4u), rem = idx % (NR*4u), n = rem >> 2, ch = idx & 3u;
        cp16ca(dst + p*(NR*80u) + n*80u + ch*16u,
               img + (size_t)p*partN + (size_t)(n0 + n)*ldk + k0 + ch*8u);
    }
}

// ---------- GEMM: C[64 x NR] = A[64 x NST*32] * B^T, bf16 3-split ----------
// 8 warps: 2 rowgroups (32m) x 4 colgroups (NT*16 n each).
template<int NST, int NT, u32 NR>
__device__ __forceinline__ void run_layer(
    const bf16* __restrict__ Aimg, u32 aldk, u32 apartN,
    const bf16* __restrict__ Bimg, u32 bldk, u32 bpartN, u32 n0,
    u32 m0, u8* smp, u32 smb, u32 tid, FragC (&c)[8])
{
#pragma unroll
    for (int i = 0; i < 2*NT; ++i) wmma::fill_fragment(c[i], 0.0f);
    const u32 warp = tid >> 5;
    const u32 rowg = warp >> 2, colg = warp & 3u;

    stageA(smb + SA_B, Aimg, aldk, apartN, m0, 0u, tid);
    stageB<NR>(smb + SB_B, Bimg, bldk, bpartN, n0, 0u, tid);
    CP_COMMIT();
#pragma unroll 1
    for (int st = 0; st < NST; ++st) {
        const u32 buf = (u32)st & 1u;
        CP_WAIT0();
        __syncthreads();
        if (st + 1 < NST) {
            stageA(smb + SA_B + (buf^1u)*SA_BUF, Aimg, aldk, apartN, m0, (u32)(st+1)*32u, tid);
            stageB<NR>(smb + SB_B + (buf^1u)*(NR*160u), Bimg, bldk, bpartN, n0, (u32)(st+1)*32u, tid);
            CP_COMMIT();
        }
        const bf16* sa = (const bf16*)(smp + SA_B + buf*SA_BUF);
        const bf16* sb = (const bf16*)(smp + SB_B + buf*(NR*160u));
#pragma unroll
        for (int ks = 0; ks < 2; ++ks) {
            FragA ah[2], al[2];
#pragma unroll
            for (int r2 = 0; r2 < 2; ++r2) {
                const bf16* ap = sa + (rowg*32u + (u32)r2*16u)*40u + (u32)ks*16u;
                wmma::load_matrix_sync(ah[r2], ap, 40);
                wmma::load_matrix_sync(al[r2], ap + 2560u, 40);        // A lo (+5120B)
            }
#pragma unroll
            for (int t = 0; t < NT; ++t) {
                const bf16* bp = sb + (colg*(u32)NT*16u + (u32)t*16u)*40u + (u32)ks*16u;
                FragB bh, bl;
                wmma::load_matrix_sync(bh, bp, 40);
                wmma::load_matrix_sync(bl, bp + (NR*40u), 40);         // B lo (+NR*80B)
#pragma unroll
                for (int r2 = 0; r2 < 2; ++r2) {
                    wmma::mma_sync(c[r2*NT + t], ah[r2], bh, c[r2*NT + t]);
                    wmma::mma_sync(c[r2*NT + t], ah[r2], bl, c[r2*NT + t]);
                    wmma::mma_sync(c[r2*NT + t], al[r2], bh, c[r2*NT + t]);
                }
            }
        }
    }
}

// ---------- epilogues ----------
__device__ __forceinline__ void epiH(FragC (&c)[8], const float* __restrict__ bias,
                                     bf16* __restrict__ img, float* __restrict__ bounce,
                                     u32 tid, u32 m0, u32 c0) {
    u32 warp = tid >> 5, lane = tid & 31u;
    u32 rowg = warp >> 2, colg = warp & 3u;
    float* bw = bounce + warp*256u;
    u32 row = lane & 15u, cg = lane >> 4;
#pragma unroll
    for (int r2 = 0; r2 < 2; ++r2)
#pragma unroll 1
    for (int t = 0; t < 4; ++t) {
        wmma::store_matrix_sync(bw, c[r2*4 + t], 16, wmma::mem_row_major);
        __syncwarp();
        const float* p = bw + row*16u + cg*8u;
        u32 col = c0 + colg*64u + (u32)t*16u + cg*8u;
        u32 m = m0 + rowg*32u + (u32)r2*16u + row;
        float4 bA = __ldg((const float4*)(bias + col));
        float4 bB = __ldg((const float4*)(bias + col + 4));
        float bb[8] = { bA.x, bA.y, bA.z, bA.w, bB.x, bB.y, bB.z, bB.w };
        alignas(16) bf16 hv[8], lv[8];
#pragma unroll
        for (int j = 0; j < 8; ++j) {
            float v = p[j] + bb[j];
            v = v / (1.0f + __expf(-v));          // SiLU
            bsplit(v, hv[j], lv[j]);
        }
        size_t gi = (size_t)m*512u + col;
        *reinterpret_cast<uint4*>(&img[gi])      = *reinterpret_cast<const uint4*>(hv);
        *reinterpret_cast<uint4*>(&img[HN + gi]) = *reinterpret_cast<const uint4*>(lv);
        __syncwarp();
    }
}

__device__ __forceinline__ void epi3(FragC (&c)[8], const float* __restrict__ b3,
                                     float coef, bool last, float* __restrict__ out,
                                     float* __restrict__ bounce, u32 tid, u32 m0, u32 c0) {
    u32 warp = tid >> 5, lane = tid & 31u;
    u32 rowg = warp >> 2, colg = warp & 3u;
    float* bw = bounce + warp*256u;
    u32 row = lane & 15u, cg = lane >> 4;
#pragma unroll
    for (int r2 = 0; r2 < 2; ++r2)
#pragma unroll 1
    for (int t = 0; t < 2; ++t) {
        wmma::store_matrix_sync(bw, c[r2*2 + t], 16, wmma::mem_row_major);
        __syncwarp();
        const float* p = bw + row*16u + cg*8u;
        u32 col = c0 + colg*32u + (u32)t*16u + cg*8u;
        u32 m = m0 + rowg*32u + (u32)r2*16u + row;
        float4 bA = __ldg((const float4*)(b3 + col));
        float4 bB = __ldg((const float4*)(b3 + col + 4));
        float bb[8] = { bA.x, bA.y, bA.z, bA.w, bB.x, bB.y, bB.z, bB.w };
        alignas(16) bf16 hv[8], lv[8];
#pragma unroll
        for (int j = 0; j < 8; ++j) {
            float x = p[j] + bb[j];
            size_t si = (size_t)m*256u + col + j;
            float s = g_State[si] + coef * x;      // exact fp32 Euler recurrence
            g_State[si] = s;
            if (last) out[si] = s;
            bsplit(s, hv[j], lv[j]);
        }
        size_t gi = (size_t)m*384u + col;          // state region of X image
        *reinterpret_cast<uint4*>(&g_X[gi])      = *reinterpret_cast<const uint4*>(hv);
        *reinterpret_cast<uint4*>(&g_X[XN + gi]) = *reinterpret_cast<const uint4*>(lv);
        __syncwarp();
    }
}

// ---------- main kernel: pair of CTAs per 64-row m-tile, N split in half ----------
__global__ void __launch_bounds__(THREADS, 2)
ode_mma(const float* __restrict__ b1, const float* __restrict__ b2,
        const float* __restrict__ b3, float* __restrict__ out) {
    extern __shared__ __align__(16) u8 smp[];
    u32 smb = (u32)__cvta_generic_to_shared(smp);
    u32 tid = threadIdx.x;
    u32 cta = blockIdx.x;
    u32 m0   = (cta >> 1) * 64u;
    u32 half = cta & 1u;
    float* bounce = (float*)(smp + SNC_B);

    FragC c[8];
    int phase = 0;
#pragma unroll 1
    for (int it = 0; it < NITER; ++it) {
        const float coef = (it == NITER - 1) ? 1.0f : DT;
        // Layer 1: X[64,384] @ W1 cols [half*256, +256)
        run_layer<12, 4, 256u>(g_X, 384u, XN, g_W1, 384u, 196608u, half*256u,
                               m0, smp, smb, tid, c);
        epiH(c, b1, g_H1, bounce, tid, m0, half*256u);
        pair_sync(cta, ++phase, tid);
        // Layer 2: H1[64,512] @ W2 cols [half*256, +256)
        run_layer<16, 4, 256u>(g_H1, 512u, HN, g_W2, 512u, 262144u, half*256u,
                               m0, smp, smb, tid, c);
        epiH(c, b2, g_H2, bounce, tid, m0, half*256u);
        pair_sync(cta, ++phase, tid);
        // Layer 3: H2[64,512] @ W3 cols [half*128, +128) -> Euler update
        run_layer<16, 2, 128u>(g_H2, 512u, HN, g_W3, 512u, 131072u, half*128u,
                               m0, smp, smb, tid, c);
        epi3(c, b3, coef, it == NITER - 1, out, bounce, tid, m0, half*128u);
        pair_sync(cta, ++phase, tid);
    }
}

extern "C" void kernel_launch(void* const* d_in, const int* in_sizes, int n_in,
                              void* d_out, int out_size) {
    const float* state = (const float*)d_in[0];
    const float* user  = (const float*)d_in[1];
    const float* W1    = (const float*)d_in[2];
    const float* b1    = (const float*)d_in[3];
    const float* W2    = (const float*)d_in[4];
    const float* b2    = (const float*)d_in[5];
    const float* W3    = (const float*)d_in[6];
    const float* b3    = (const float*)d_in[7];
    float* out = (float*)d_out;

    prep_all<<<12288, 256>>>(state, user, W1, W2, W3);
    cudaFuncSetAttribute(ode_mma, cudaFuncAttributeMaxDynamicSharedMemorySize, SMEM_SZ);
    ode_mma<<<256, THREADS, SMEM_SZ>>>(b1, b2, b3, out);
}